// round 1
// baseline (speedup 1.0000x reference)
#include <cuda_runtime.h>

#define BATCH 2
#define C 128
#define H 96
#define W 96
#define HEADS 4
#define DHEAD 32
#define PAD 2
#define INNER 128
#define HW (H * W)
#define HP (H + 2 * PAD)
#define WP (W + 2 * PAD)

// Scratch (zero-initialized at module load; padding regions never written -> stay zero)
__device__ float g_q[(size_t)BATCH * HW * INNER];          // [b][p][h*32+d]
__device__ float g_kpad[(size_t)BATCH * HP * WP * INNER];  // [b][y+2][x+2][h*32+d]
__device__ float g_vpad[(size_t)BATCH * HP * WP * INNER];
__device__ float g_obuf[(size_t)BATCH * INNER * HW];       // [b][ch][p]

// ---------------------------------------------------------------------------
// Kernel 1: QKV projection.  out[o,p] = sum_c W[o,c] * x[b,c,p]
// Tiled SGEMM: BM=128 (out ch), BN=128 (pixels), BK=16, 256 threads, 8x8/thread
// grid = (HW/128, 3 {q,k,v}, BATCH)
// ---------------------------------------------------------------------------
__global__ __launch_bounds__(256) void qkv_kernel(
    const float* __restrict__ x, const float* __restrict__ wq,
    const float* __restrict__ wk, const float* __restrict__ wv)
{
    const int pb  = blockIdx.x;
    const int mat = blockIdx.y;   // 0=q, 1=k, 2=v
    const int b   = blockIdx.z;
    const float* __restrict__ wsel = (mat == 0) ? wq : (mat == 1) ? wk : wv;
    const float* __restrict__ X = x + (size_t)b * C * HW + pb * 128;

    __shared__ float Ws[16][128];   // [k][o]
    __shared__ float Xs[16][128];   // [k][p]

    const int tid = threadIdx.x;
    const int tm = tid >> 4;    // 0..15
    const int tn = tid & 15;    // 0..15

    float acc[8][8];
#pragma unroll
    for (int i = 0; i < 8; i++)
#pragma unroll
        for (int j = 0; j < 8; j++) acc[i][j] = 0.f;

    for (int k0 = 0; k0 < C; k0 += 16) {
        // W tile: 128 rows(o) x 16 cols(k) = 512 float4, 2 per thread
#pragma unroll
        for (int i = 0; i < 2; i++) {
            int li = tid * 2 + i;          // 0..511
            int o  = li >> 2;
            int kq = (li & 3) * 4;
            float4 w4 = *(const float4*)(wsel + o * C + k0 + kq);
            Ws[kq + 0][o] = w4.x;
            Ws[kq + 1][o] = w4.y;
            Ws[kq + 2][o] = w4.z;
            Ws[kq + 3][o] = w4.w;
        }
        // X tile: 16 rows(k) x 128 cols(p)
#pragma unroll
        for (int i = 0; i < 2; i++) {
            int li = tid * 2 + i;
            int kr = li >> 5;              // 0..15
            int pq = (li & 31) * 4;
            *(float4*)&Xs[kr][pq] = *(const float4*)(X + (size_t)(k0 + kr) * HW + pq);
        }
        __syncthreads();
#pragma unroll
        for (int kk = 0; kk < 16; kk++) {
            float a[8], bb[8];
#pragma unroll
            for (int i = 0; i < 8; i++) a[i] = Ws[kk][tm * 8 + i];
#pragma unroll
            for (int j = 0; j < 8; j++) bb[j] = Xs[kk][tn * 8 + j];
#pragma unroll
            for (int i = 0; i < 8; i++)
#pragma unroll
                for (int j = 0; j < 8; j++)
                    acc[i][j] = fmaf(a[i], bb[j], acc[i][j]);
        }
        __syncthreads();
    }

    const int p0 = pb * 128;
#pragma unroll
    for (int j = 0; j < 8; j++) {
        int p = p0 + tn * 8 + j;
        float* dst;
        if (mat == 0) {
            dst = g_q + ((size_t)b * HW + p) * INNER + tm * 8;
        } else {
            int yy = p / W, xx = p - yy * W;
            float* base = (mat == 1) ? g_kpad : g_vpad;
            dst = base + (((size_t)b * HP + yy + PAD) * WP + (xx + PAD)) * INNER + tm * 8;
        }
        *(float4*)(dst)     = make_float4(acc[0][j], acc[1][j], acc[2][j], acc[3][j]);
        *(float4*)(dst + 4) = make_float4(acc[4][j], acc[5][j], acc[6][j], acc[7][j]);
    }
}

// ---------------------------------------------------------------------------
// Kernel 2: window attention. 1 thread = 1 (pixel, head).
// grid = (HW/128, HEADS*BATCH), 128 threads
// ---------------------------------------------------------------------------
__global__ void attn_kernel()
{
    const int p = blockIdx.x * 128 + threadIdx.x;
    const int h = blockIdx.y & 3;
    const int b = blockIdx.y >> 2;
    const int y = p / W;
    const int x = p - y * W;

    const float* __restrict__ qp =
        g_q + ((size_t)b * HW + p) * INNER + h * DHEAD;
    float qr[DHEAD];
#pragma unroll
    for (int d = 0; d < DHEAD; d += 4) {
        float4 v = *(const float4*)(qp + d);
        qr[d] = v.x; qr[d + 1] = v.y; qr[d + 2] = v.z; qr[d + 3] = v.w;
    }

    // base address: padded coords (y+di, x+dj) for di,dj in [0,5)
    const size_t pixbase = ((size_t)b * HP + y) * WP + x;
    const float* __restrict__ kbase = g_kpad + pixbase * INNER + h * DHEAD;
    const float* __restrict__ vbase = g_vpad + pixbase * INNER + h * DHEAD;

    const float scale = 0.17677669529663687f;  // 1/sqrt(32)
    float sc[25];
#pragma unroll
    for (int n = 0; n < 25; n++) {
        const int di = n / 5, dj = n - 5 * (n / 5);
        const float* kp = kbase + (size_t)(di * WP + dj) * INNER;
        float s = 0.f;
#pragma unroll
        for (int d = 0; d < DHEAD; d += 4) {
            float4 kv = *(const float4*)(kp + d);
            s = fmaf(qr[d], kv.x, s);
            s = fmaf(qr[d + 1], kv.y, s);
            s = fmaf(qr[d + 2], kv.z, s);
            s = fmaf(qr[d + 3], kv.w, s);
        }
        sc[n] = s * scale;
    }

    float m = sc[0];
#pragma unroll
    for (int n = 1; n < 25; n++) m = fmaxf(m, sc[n]);
    float sum = 0.f;
#pragma unroll
    for (int n = 0; n < 25; n++) {
        float e = __expf(sc[n] - m);
        sc[n] = e;
        sum += e;
    }
    const float inv = 1.f / sum;

    float out[DHEAD];
#pragma unroll
    for (int d = 0; d < DHEAD; d++) out[d] = 0.f;
#pragma unroll
    for (int n = 0; n < 25; n++) {
        const int di = n / 5, dj = n - 5 * (n / 5);
        const float wgt = sc[n];
        const float* vp = vbase + (size_t)(di * WP + dj) * INNER;
#pragma unroll
        for (int d = 0; d < DHEAD; d += 4) {
            float4 vv = *(const float4*)(vp + d);
            out[d]     = fmaf(wgt, vv.x, out[d]);
            out[d + 1] = fmaf(wgt, vv.y, out[d + 1]);
            out[d + 2] = fmaf(wgt, vv.z, out[d + 2]);
            out[d + 3] = fmaf(wgt, vv.w, out[d + 3]);
        }
    }

    float* ob = g_obuf + ((size_t)b * INNER + h * DHEAD) * HW + p;
#pragma unroll
    for (int d = 0; d < DHEAD; d++)
        ob[(size_t)d * HW] = out[d] * inv;
}

// ---------------------------------------------------------------------------
// Kernel 3: output projection.  out[c,p] = sum_i wproj[c,i] * obuf[b,i,p]
// Same SGEMM tiling; stores NCHW.
// grid = (HW/128, 1, BATCH)
// ---------------------------------------------------------------------------
__global__ __launch_bounds__(256) void proj_kernel(
    const float* __restrict__ wproj, float* __restrict__ outp)
{
    const int pb = blockIdx.x;
    const int b  = blockIdx.z;
    const float* __restrict__ X = g_obuf + (size_t)b * INNER * HW + pb * 128;

    __shared__ float Ws[16][128];
    __shared__ float Xs[16][128];

    const int tid = threadIdx.x;
    const int tm = tid >> 4;
    const int tn = tid & 15;

    float acc[8][8];
#pragma unroll
    for (int i = 0; i < 8; i++)
#pragma unroll
        for (int j = 0; j < 8; j++) acc[i][j] = 0.f;

    for (int k0 = 0; k0 < INNER; k0 += 16) {
#pragma unroll
        for (int i = 0; i < 2; i++) {
            int li = tid * 2 + i;
            int o  = li >> 2;
            int kq = (li & 3) * 4;
            float4 w4 = *(const float4*)(wproj + o * INNER + k0 + kq);
            Ws[kq + 0][o] = w4.x;
            Ws[kq + 1][o] = w4.y;
            Ws[kq + 2][o] = w4.z;
            Ws[kq + 3][o] = w4.w;
        }
#pragma unroll
        for (int i = 0; i < 2; i++) {
            int li = tid * 2 + i;
            int kr = li >> 5;
            int pq = (li & 31) * 4;
            *(float4*)&Xs[kr][pq] = *(const float4*)(X + (size_t)(k0 + kr) * HW + pq);
        }
        __syncthreads();
#pragma unroll
        for (int kk = 0; kk < 16; kk++) {
            float a[8], bb[8];
#pragma unroll
            for (int i = 0; i < 8; i++) a[i] = Ws[kk][tm * 8 + i];
#pragma unroll
            for (int j = 0; j < 8; j++) bb[j] = Xs[kk][tn * 8 + j];
#pragma unroll
            for (int i = 0; i < 8; i++)
#pragma unroll
                for (int j = 0; j < 8; j++)
                    acc[i][j] = fmaf(a[i], bb[j], acc[i][j]);
        }
        __syncthreads();
    }

    const int p0 = pb * 128;
#pragma unroll
    for (int i = 0; i < 8; i++) {
        int o = tm * 8 + i;
        float* dst = outp + ((size_t)b * C + o) * HW + p0 + tn * 8;
        *(float4*)(dst)     = make_float4(acc[i][0], acc[i][1], acc[i][2], acc[i][3]);
        *(float4*)(dst + 4) = make_float4(acc[i][4], acc[i][5], acc[i][6], acc[i][7]);
    }
}

extern "C" void kernel_launch(void* const* d_in, const int* in_sizes, int n_in,
                              void* d_out, int out_size)
{
    const float* x     = (const float*)d_in[0];
    const float* wq    = (const float*)d_in[1];
    const float* wk    = (const float*)d_in[2];
    const float* wv    = (const float*)d_in[3];
    const float* wproj = (const float*)d_in[4];
    float* outp = (float*)d_out;

    qkv_kernel<<<dim3(HW / 128, 3, BATCH), 256>>>(x, wq, wk, wv);
    attn_kernel<<<dim3(HW / 128, HEADS * BATCH), 128>>>();
    proj_kernel<<<dim3(HW / 128, 1, BATCH), 256>>>(wproj, outp);
}

// round 2
// speedup vs baseline: 1.9849x; 1.9849x over previous
#include <cuda_runtime.h>

#define BATCH 2
#define C 128
#define H 96
#define W 96
#define HEADS 4
#define DHEAD 32
#define PAD 2
#define INNER 128
#define HW (H * W)
#define HP (H + 2 * PAD)
#define WP (W + 2 * PAD)

typedef unsigned long long u64;

// Scratch (zero-initialized at module load; padding regions never written -> stay zero)
__device__ float g_q[(size_t)BATCH * HW * INNER];          // [b][p][h*32+d]
__device__ float g_kpad[(size_t)BATCH * HP * WP * INNER];  // [b][y+2][x+2][h*32+d]
__device__ float g_vpad[(size_t)BATCH * HP * WP * INNER];
__device__ float g_obuf[(size_t)BATCH * INNER * HW];       // [b][ch][p]

#define FFMA2(d, a, b) \
    asm("fma.rn.f32x2 %0, %1, %2, %0;" : "+l"(d) : "l"(a), "l"(b))
#define PACK2(d, s) \
    asm("mov.b64 %0, {%1, %1};" : "=l"(d) : "f"(s))

// ---------------------------------------------------------------------------
// Kernel 1: QKV projection.  out[o,p] = sum_c W[o,c] * x[b,c,p]
// BM=128 (out ch), BN=128 (pixels), BK=16, 256 threads.
// Thread tile: 8 rows (tm*8+i) x 8 cols in two groups {tn*4..+3, 64+tn*4..+3}.
// Inner product uses fma.rn.f32x2 (2 cols per op).
// ---------------------------------------------------------------------------
__global__ __launch_bounds__(256) void qkv_kernel(
    const float* __restrict__ x, const float* __restrict__ wq,
    const float* __restrict__ wk, const float* __restrict__ wv)
{
    const int pb  = blockIdx.x;
    const int mat = blockIdx.y;   // 0=q, 1=k, 2=v
    const int b   = blockIdx.z;
    const float* __restrict__ wsel = (mat == 0) ? wq : (mat == 1) ? wk : wv;
    const float* __restrict__ X = x + (size_t)b * C * HW + pb * 128;

    __shared__ float Ws[16][128];   // [k][o]
    __shared__ float Xs[16][128];   // [k][p]

    const int tid = threadIdx.x;
    const int tm = tid >> 4;    // 0..15
    const int tn = tid & 15;    // 0..15

    u64 acc[8][4];              // [row i][col-pair]: pairs (g*64+tn*4 + {0,1}|{2,3})
#pragma unroll
    for (int i = 0; i < 8; i++)
#pragma unroll
        for (int j = 0; j < 4; j++) acc[i][j] = 0ull;

    for (int k0 = 0; k0 < C; k0 += 16) {
#pragma unroll
        for (int i = 0; i < 2; i++) {
            int li = tid * 2 + i;          // 0..511
            int o  = li >> 2;
            int kq = (li & 3) * 4;
            float4 w4 = *(const float4*)(wsel + o * C + k0 + kq);
            Ws[kq + 0][o] = w4.x;
            Ws[kq + 1][o] = w4.y;
            Ws[kq + 2][o] = w4.z;
            Ws[kq + 3][o] = w4.w;
        }
#pragma unroll
        for (int i = 0; i < 2; i++) {
            int li = tid * 2 + i;
            int kr = li >> 5;              // 0..15
            int pq = (li & 31) * 4;
            *(float4*)&Xs[kr][pq] = *(const float4*)(X + (size_t)(k0 + kr) * HW + pq);
        }
        __syncthreads();
#pragma unroll
        for (int kk = 0; kk < 16; kk++) {
            u64 bq[4];
            bq[0] = *(const u64*)&Xs[kk][tn * 4];
            bq[1] = *(const u64*)&Xs[kk][tn * 4 + 2];
            bq[2] = *(const u64*)&Xs[kk][64 + tn * 4];
            bq[3] = *(const u64*)&Xs[kk][64 + tn * 4 + 2];
            float4 wa0 = *(const float4*)&Ws[kk][tm * 8];
            float4 wa1 = *(const float4*)&Ws[kk][tm * 8 + 4];
            float av[8] = {wa0.x, wa0.y, wa0.z, wa0.w, wa1.x, wa1.y, wa1.z, wa1.w};
#pragma unroll
            for (int i = 0; i < 8; i++) {
                u64 ad;
                PACK2(ad, av[i]);
                FFMA2(acc[i][0], ad, bq[0]);
                FFMA2(acc[i][1], ad, bq[1]);
                FFMA2(acc[i][2], ad, bq[2]);
                FFMA2(acc[i][3], ad, bq[3]);
            }
        }
        __syncthreads();
    }

    // unpack: r[i][j] = row tm*8+i, col group g=j>>2: (j>>2)*64 + tn*4 + (j&3)
    float r[8][8];
#pragma unroll
    for (int i = 0; i < 8; i++)
#pragma unroll
        for (int j = 0; j < 4; j++) {
            float2 f = *(float2*)&acc[i][j];
            r[i][2 * j]     = f.x;
            r[i][2 * j + 1] = f.y;
        }

    const int p0 = pb * 128;
#pragma unroll
    for (int j = 0; j < 8; j++) {
        int col = (j >> 2) * 64 + tn * 4 + (j & 3);
        int p = p0 + col;
        float* dst;
        if (mat == 0) {
            dst = g_q + ((size_t)b * HW + p) * INNER + tm * 8;
        } else {
            int yy = p / W, xx = p - yy * W;
            float* base = (mat == 1) ? g_kpad : g_vpad;
            dst = base + (((size_t)b * HP + yy + PAD) * WP + (xx + PAD)) * INNER + tm * 8;
        }
        *(float4*)(dst)     = make_float4(r[0][j], r[1][j], r[2][j], r[3][j]);
        *(float4*)(dst + 4) = make_float4(r[4][j], r[5][j], r[6][j], r[7][j]);
    }
}

// ---------------------------------------------------------------------------
// Kernel 2: window attention, smem-tiled.
// Block = 32x4 pixel tile, one (b,h). 128 threads, 1 thread per pixel.
// Padded tile 36x8 pixels staged in smem as [dg][pix] float4 (dg-stride 289
// to avoid bank conflicts both on store and load).
// ---------------------------------------------------------------------------
#define TX 32
#define TY 4
#define PWT (TX + 4)     // 36
#define PHT (TY + 4)     // 8
#define NPIX (PWT * PHT) // 288
#define DGS 289          // padded stride between dg planes (in float4)
#define ATTN_SMEM (2 * 8 * DGS * 16)

__global__ __launch_bounds__(128) void attn_kernel()
{
    extern __shared__ float4 sm4[];
    float4* ks4 = sm4;
    float4* vs4 = sm4 + 8 * DGS;

    const int t  = threadIdx.x;
    const int x0 = blockIdx.x * TX;
    const int y0 = blockIdx.y * TY;
    const int h  = blockIdx.z & 3;
    const int b  = blockIdx.z >> 2;

    const float* __restrict__ kg =
        g_kpad + (((size_t)b * HP + y0) * WP + x0) * INNER + h * DHEAD;
    const float* __restrict__ vg =
        g_vpad + (((size_t)b * HP + y0) * WP + x0) * INNER + h * DHEAD;

    // stage k/v halo tile: idx = pp*8 + dg  (8 consecutive threads read one
    // pixel's contiguous 128B -> coalesced; smem store conflict-free via DGS)
#pragma unroll
    for (int i = t; i < NPIX * 8; i += 128) {
        int pp = i >> 3, dg = i & 7;
        int py = pp / PWT, px = pp - py * PWT;
        size_t goff = ((size_t)py * WP + px) * INNER + dg * 4;
        ks4[dg * DGS + pp] = *(const float4*)(kg + goff);
        vs4[dg * DGS + pp] = *(const float4*)(vg + goff);
    }

    const int tx = t & 31, ty = t >> 5;
    const int p = (y0 + ty) * W + x0 + tx;
    float4 q4[8];
    const float* qp = g_q + ((size_t)b * HW + p) * INNER + h * DHEAD;
#pragma unroll
    for (int dg = 0; dg < 8; dg++) q4[dg] = *(const float4*)(qp + dg * 4);

    __syncthreads();

    const float scale = 0.17677669529663687f;  // 1/sqrt(32)
    float sc[25];
#pragma unroll
    for (int n = 0; n < 25; n++) {
        const int di = n / 5, dj = n - 5 * (n / 5);
        const int pix = (ty + di) * PWT + (tx + dj);
        float s = 0.f;
#pragma unroll
        for (int dg = 0; dg < 8; dg++) {
            float4 kv = ks4[dg * DGS + pix];
            s = fmaf(q4[dg].x, kv.x, s);
            s = fmaf(q4[dg].y, kv.y, s);
            s = fmaf(q4[dg].z, kv.z, s);
            s = fmaf(q4[dg].w, kv.w, s);
        }
        sc[n] = s * scale;
    }

    float m = sc[0];
#pragma unroll
    for (int n = 1; n < 25; n++) m = fmaxf(m, sc[n]);
    float sum = 0.f;
#pragma unroll
    for (int n = 0; n < 25; n++) {
        float e = __expf(sc[n] - m);
        sc[n] = e;
        sum += e;
    }
    const float inv = 1.f / sum;

    float4 o4[8];
#pragma unroll
    for (int dg = 0; dg < 8; dg++) o4[dg] = make_float4(0.f, 0.f, 0.f, 0.f);
#pragma unroll
    for (int n = 0; n < 25; n++) {
        const int di = n / 5, dj = n - 5 * (n / 5);
        const int pix = (ty + di) * PWT + (tx + dj);
        const float wgt = sc[n];
#pragma unroll
        for (int dg = 0; dg < 8; dg++) {
            float4 vv = vs4[dg * DGS + pix];
            o4[dg].x = fmaf(wgt, vv.x, o4[dg].x);
            o4[dg].y = fmaf(wgt, vv.y, o4[dg].y);
            o4[dg].z = fmaf(wgt, vv.z, o4[dg].z);
            o4[dg].w = fmaf(wgt, vv.w, o4[dg].w);
        }
    }

    float* ob = g_obuf + ((size_t)b * INNER + h * DHEAD) * HW + p;
#pragma unroll
    for (int dg = 0; dg < 8; dg++) {
        ob[(size_t)(dg * 4 + 0) * HW] = o4[dg].x * inv;
        ob[(size_t)(dg * 4 + 1) * HW] = o4[dg].y * inv;
        ob[(size_t)(dg * 4 + 2) * HW] = o4[dg].z * inv;
        ob[(size_t)(dg * 4 + 3) * HW] = o4[dg].w * inv;
    }
}

// ---------------------------------------------------------------------------
// Kernel 3: output projection.  out[c,p] = sum_i wproj[c,i] * obuf[b,i,p]
// Same FFMA2 tiling; stores NCHW.
// ---------------------------------------------------------------------------
__global__ __launch_bounds__(256) void proj_kernel(
    const float* __restrict__ wproj, float* __restrict__ outp)
{
    const int pb = blockIdx.x;
    const int b  = blockIdx.z;
    const float* __restrict__ X = g_obuf + (size_t)b * INNER * HW + pb * 128;

    __shared__ float Ws[16][128];
    __shared__ float Xs[16][128];

    const int tid = threadIdx.x;
    const int tm = tid >> 4;
    const int tn = tid & 15;

    u64 acc[8][4];
#pragma unroll
    for (int i = 0; i < 8; i++)
#pragma unroll
        for (int j = 0; j < 4; j++) acc[i][j] = 0ull;

    for (int k0 = 0; k0 < INNER; k0 += 16) {
#pragma unroll
        for (int i = 0; i < 2; i++) {
            int li = tid * 2 + i;
            int o  = li >> 2;
            int kq = (li & 3) * 4;
            float4 w4 = *(const float4*)(wproj + o * INNER + k0 + kq);
            Ws[kq + 0][o] = w4.x;
            Ws[kq + 1][o] = w4.y;
            Ws[kq + 2][o] = w4.z;
            Ws[kq + 3][o] = w4.w;
        }
#pragma unroll
        for (int i = 0; i < 2; i++) {
            int li = tid * 2 + i;
            int kr = li >> 5;
            int pq = (li & 31) * 4;
            *(float4*)&Xs[kr][pq] = *(const float4*)(X + (size_t)(k0 + kr) * HW + pq);
        }
        __syncthreads();
#pragma unroll
        for (int kk = 0; kk < 16; kk++) {
            u64 bq[4];
            bq[0] = *(const u64*)&Xs[kk][tn * 4];
            bq[1] = *(const u64*)&Xs[kk][tn * 4 + 2];
            bq[2] = *(const u64*)&Xs[kk][64 + tn * 4];
            bq[3] = *(const u64*)&Xs[kk][64 + tn * 4 + 2];
            float4 wa0 = *(const float4*)&Ws[kk][tm * 8];
            float4 wa1 = *(const float4*)&Ws[kk][tm * 8 + 4];
            float av[8] = {wa0.x, wa0.y, wa0.z, wa0.w, wa1.x, wa1.y, wa1.z, wa1.w};
#pragma unroll
            for (int i = 0; i < 8; i++) {
                u64 ad;
                PACK2(ad, av[i]);
                FFMA2(acc[i][0], ad, bq[0]);
                FFMA2(acc[i][1], ad, bq[1]);
                FFMA2(acc[i][2], ad, bq[2]);
                FFMA2(acc[i][3], ad, bq[3]);
            }
        }
        __syncthreads();
    }

    const int p0 = pb * 128;
#pragma unroll
    for (int i = 0; i < 8; i++) {
        int o = tm * 8 + i;
        float* dst = outp + ((size_t)b * C + o) * HW + p0;
        float2 f0 = *(float2*)&acc[i][0];
        float2 f1 = *(float2*)&acc[i][1];
        float2 f2 = *(float2*)&acc[i][2];
        float2 f3 = *(float2*)&acc[i][3];
        *(float4*)(dst + tn * 4)      = make_float4(f0.x, f0.y, f1.x, f1.y);
        *(float4*)(dst + 64 + tn * 4) = make_float4(f2.x, f2.y, f3.x, f3.y);
    }
}

extern "C" void kernel_launch(void* const* d_in, const int* in_sizes, int n_in,
                              void* d_out, int out_size)
{
    const float* x     = (const float*)d_in[0];
    const float* wq    = (const float*)d_in[1];
    const float* wk    = (const float*)d_in[2];
    const float* wv    = (const float*)d_in[3];
    const float* wproj = (const float*)d_in[4];
    float* outp = (float*)d_out;

    cudaFuncSetAttribute(attn_kernel,
                         cudaFuncAttributeMaxDynamicSharedMemorySize, ATTN_SMEM);

    qkv_kernel<<<dim3(HW / 128, 3, BATCH), 256>>>(x, wq, wk, wv);
    attn_kernel<<<dim3(W / TX, H / TY, HEADS * BATCH), 128, ATTN_SMEM>>>();
    proj_kernel<<<dim3(HW / 128, 1, BATCH), 256>>>(wproj, outp);
}

// round 3
// speedup vs baseline: 2.3637x; 1.1909x over previous
#include <cuda_runtime.h>

#define BATCH 2
#define C 128
#define H 96
#define W 96
#define HEADS 4
#define DHEAD 32
#define PAD 2
#define INNER 128
#define HW (H * W)
#define HP (H + 2 * PAD)
#define WP (W + 2 * PAD)

typedef unsigned long long u64;

// Scratch (zero-initialized at module load; padding regions never written -> stay zero)
__device__ float g_q[(size_t)BATCH * HW * INNER];          // [b][p][h*32+d]
__device__ float g_kpad[(size_t)BATCH * HP * WP * INNER];  // [b][y+2][x+2][h*32+d]
__device__ float g_vpad[(size_t)BATCH * HP * WP * INNER];
__device__ float g_obuf[(size_t)BATCH * INNER * HW];       // [b][ch][p]
__device__ float g_wt[4][C * INNER];                       // transposed weights [k][o]

#define FFMA2(d, a, b) \
    asm("fma.rn.f32x2 %0, %1, %2, %0;" : "+l"(d) : "l"(a), "l"(b))
#define PACK2(d, s) \
    asm("mov.b64 %0, {%1, %1};" : "=l"(d) : "f"(s))

__device__ __forceinline__ void cp16(void* smem, const void* g) {
    unsigned s = (unsigned)__cvta_generic_to_shared(smem);
    asm volatile("cp.async.cg.shared.global [%0], [%1], 16;" :: "r"(s), "l"(g));
}
#define CP_COMMIT() asm volatile("cp.async.commit_group;")
#define CP_WAIT(n)  asm volatile("cp.async.wait_group %0;" :: "n"(n))

// ---------------------------------------------------------------------------
// Kernel 0: transpose all 4 weight matrices into g_wt[mat][k][o]
// ---------------------------------------------------------------------------
__global__ __launch_bounds__(256) void wtrans_kernel(
    const float* __restrict__ wq, const float* __restrict__ wk,
    const float* __restrict__ wv, const float* __restrict__ wp)
{
    const float* __restrict__ src =
        (blockIdx.y == 0) ? wq : (blockIdx.y == 1) ? wk : (blockIdx.y == 2) ? wv : wp;
    int idx = blockIdx.x * 256 + threadIdx.x;   // grid.x = 64
    int o = idx >> 7, k = idx & 127;
    g_wt[blockIdx.y][k * 128 + o] = src[idx];
}

// ---------------------------------------------------------------------------
// GEMM compute: BM=128, BN=128, BK=16, 256 threads, FFMA2, double-buffered
// ---------------------------------------------------------------------------
__device__ __forceinline__ void gemm_stage(
    float (*Ws)[16][128], float (*Xs)[16][128], int s,
    const float* __restrict__ wt, const float* __restrict__ X,
    int k0, int tid, int xld)
{
#pragma unroll
    for (int i = 0; i < 2; i++) {
        int li = tid * 2 + i;          // 0..511
        int kr = li >> 5;              // 0..15
        int cq = (li & 31) * 4;        // 0..124
        cp16(&Ws[s][kr][cq], wt + (k0 + kr) * 128 + cq);
        cp16(&Xs[s][kr][cq], X + (size_t)(k0 + kr) * xld + cq);
    }
    CP_COMMIT();
}

__device__ __forceinline__ void gemm_compute(
    const float (*Ws)[16][128], const float (*Xs)[16][128], int s,
    int tm, int tn, u64 acc[8][4])
{
#pragma unroll
    for (int kk = 0; kk < 16; kk++) {
        u64 bq[4];
        bq[0] = *(const u64*)&Xs[s][kk][tn * 4];
        bq[1] = *(const u64*)&Xs[s][kk][tn * 4 + 2];
        bq[2] = *(const u64*)&Xs[s][kk][64 + tn * 4];
        bq[3] = *(const u64*)&Xs[s][kk][64 + tn * 4 + 2];
        float4 wa0 = *(const float4*)&Ws[s][kk][tm * 8];
        float4 wa1 = *(const float4*)&Ws[s][kk][tm * 8 + 4];
        float av[8] = {wa0.x, wa0.y, wa0.z, wa0.w, wa1.x, wa1.y, wa1.z, wa1.w};
#pragma unroll
        for (int i = 0; i < 8; i++) {
            u64 ad;
            PACK2(ad, av[i]);
            FFMA2(acc[i][0], ad, bq[0]);
            FFMA2(acc[i][1], ad, bq[1]);
            FFMA2(acc[i][2], ad, bq[2]);
            FFMA2(acc[i][3], ad, bq[3]);
        }
    }
}

// ---------------------------------------------------------------------------
// Kernel 1: QKV projection.  out[o,p] = sum_c Wt[c,o] * x[b,c,p]
// ---------------------------------------------------------------------------
__global__ __launch_bounds__(256) void qkv_kernel(const float* __restrict__ x)
{
    const int pb  = blockIdx.x;
    const int mat = blockIdx.y;   // 0=q, 1=k, 2=v
    const int b   = blockIdx.z;
    const float* __restrict__ wt = g_wt[mat];
    const float* __restrict__ X = x + (size_t)b * C * HW + pb * 128;

    __shared__ float Ws[2][16][128];
    __shared__ float Xs[2][16][128];

    const int tid = threadIdx.x;
    const int tm = tid >> 4;    // 0..15
    const int tn = tid & 15;    // 0..15

    u64 acc[8][4];
#pragma unroll
    for (int i = 0; i < 8; i++)
#pragma unroll
        for (int j = 0; j < 4; j++) acc[i][j] = 0ull;

    gemm_stage(Ws, Xs, 0, wt, X, 0, tid, HW);
#pragma unroll
    for (int t = 0; t < 8; t++) {
        if (t < 7) {
            gemm_stage(Ws, Xs, (t + 1) & 1, wt, X, (t + 1) * 16, tid, HW);
            CP_WAIT(1);
        } else {
            CP_WAIT(0);
        }
        __syncthreads();
        gemm_compute(Ws, Xs, t & 1, tm, tn, acc);
        __syncthreads();
    }

    float r[8][8];
#pragma unroll
    for (int i = 0; i < 8; i++)
#pragma unroll
        for (int j = 0; j < 4; j++) {
            float2 f = *(float2*)&acc[i][j];
            r[i][2 * j]     = f.x;
            r[i][2 * j + 1] = f.y;
        }

    const int p0 = pb * 128;
#pragma unroll
    for (int j = 0; j < 8; j++) {
        int col = (j >> 2) * 64 + tn * 4 + (j & 3);
        int p = p0 + col;
        float* dst;
        if (mat == 0) {
            dst = g_q + ((size_t)b * HW + p) * INNER + tm * 8;
        } else {
            int yy = p / W, xx = p - yy * W;
            float* base = (mat == 1) ? g_kpad : g_vpad;
            dst = base + (((size_t)b * HP + yy + PAD) * WP + (xx + PAD)) * INNER + tm * 8;
        }
        *(float4*)(dst)     = make_float4(r[0][j], r[1][j], r[2][j], r[3][j]);
        *(float4*)(dst + 4) = make_float4(r[4][j], r[5][j], r[6][j], r[7][j]);
    }
}

// ---------------------------------------------------------------------------
// Kernel 2: window attention, smem-tiled, f32x2.
// Block = 32x8 pixel tile, one (b,h). 256 threads, 1 thread per pixel.
// Padded tile 36x12 staged in smem as [dg][pix] float4, dg-stride 433.
// ---------------------------------------------------------------------------
#define TX 32
#define TY 8
#define PWT (TX + 4)     // 36
#define PHT (TY + 4)     // 12
#define NPIX (PWT * PHT) // 432
#define DGS 433
#define ATTN_SMEM (2 * 8 * DGS * 16)

__global__ __launch_bounds__(256) void attn_kernel()
{
    extern __shared__ float4 sm4[];
    float4* ks4 = sm4;
    float4* vs4 = sm4 + 8 * DGS;

    const int t  = threadIdx.x;
    const int x0 = blockIdx.x * TX;
    const int y0 = blockIdx.y * TY;
    const int h  = blockIdx.z & 3;
    const int b  = blockIdx.z >> 2;

    const float* __restrict__ kg =
        g_kpad + (((size_t)b * HP + y0) * WP + x0) * INNER + h * DHEAD;
    const float* __restrict__ vg =
        g_vpad + (((size_t)b * HP + y0) * WP + x0) * INNER + h * DHEAD;

#pragma unroll
    for (int i = t; i < NPIX * 8; i += 256) {
        int pp = i >> 3, dg = i & 7;
        int py = pp / PWT, px = pp - py * PWT;
        size_t goff = ((size_t)py * WP + px) * INNER + dg * 4;
        ks4[dg * DGS + pp] = *(const float4*)(kg + goff);
        vs4[dg * DGS + pp] = *(const float4*)(vg + goff);
    }

    const int tx = t & 31, ty = t >> 5;
    const int p = (y0 + ty) * W + x0 + tx;
    u64 q2[16];
    const float* qp = g_q + ((size_t)b * HW + p) * INNER + h * DHEAD;
#pragma unroll
    for (int dg = 0; dg < 8; dg++) {
        ulonglong2 v = *(const ulonglong2*)(qp + dg * 4);
        q2[dg * 2] = v.x; q2[dg * 2 + 1] = v.y;
    }

    __syncthreads();

    const float scale = 0.17677669529663687f;  // 1/sqrt(32)
    float sc[25];
#pragma unroll
    for (int n = 0; n < 25; n++) {
        const int di = n / 5, dj = n - 5 * (n / 5);
        const int pix = (ty + di) * PWT + (tx + dj);
        u64 s2 = 0ull;
#pragma unroll
        for (int dg = 0; dg < 8; dg++) {
            ulonglong2 kv = *(const ulonglong2*)&ks4[dg * DGS + pix];
            FFMA2(s2, q2[dg * 2], kv.x);
            FFMA2(s2, q2[dg * 2 + 1], kv.y);
        }
        float2 sf = *(float2*)&s2;
        sc[n] = (sf.x + sf.y) * scale;
    }

    float m = sc[0];
#pragma unroll
    for (int n = 1; n < 25; n++) m = fmaxf(m, sc[n]);
    float sum = 0.f;
#pragma unroll
    for (int n = 0; n < 25; n++) {
        float e = __expf(sc[n] - m);
        sc[n] = e;
        sum += e;
    }
    const float inv = 1.f / sum;

    u64 o2[16];
#pragma unroll
    for (int i = 0; i < 16; i++) o2[i] = 0ull;
#pragma unroll
    for (int n = 0; n < 25; n++) {
        const int di = n / 5, dj = n - 5 * (n / 5);
        const int pix = (ty + di) * PWT + (tx + dj);
        u64 w2;
        PACK2(w2, sc[n]);
#pragma unroll
        for (int dg = 0; dg < 8; dg++) {
            ulonglong2 vv = *(const ulonglong2*)&vs4[dg * DGS + pix];
            FFMA2(o2[dg * 2], w2, vv.x);
            FFMA2(o2[dg * 2 + 1], w2, vv.y);
        }
    }

    float* ob = g_obuf + ((size_t)b * INNER + h * DHEAD) * HW + p;
#pragma unroll
    for (int i = 0; i < 16; i++) {
        float2 f = *(float2*)&o2[i];
        ob[(size_t)(i * 2 + 0) * HW] = f.x * inv;
        ob[(size_t)(i * 2 + 1) * HW] = f.y * inv;
    }
}

// ---------------------------------------------------------------------------
// Kernel 3: output projection.  out[c,p] = sum_i wt3[i,c] * obuf[b,i,p]
// ---------------------------------------------------------------------------
__global__ __launch_bounds__(256) void proj_kernel(float* __restrict__ outp)
{
    const int pb = blockIdx.x;
    const int b  = blockIdx.z;
    const float* __restrict__ wt = g_wt[3];
    const float* __restrict__ X = g_obuf + (size_t)b * INNER * HW + pb * 128;

    __shared__ float Ws[2][16][128];
    __shared__ float Xs[2][16][128];

    const int tid = threadIdx.x;
    const int tm = tid >> 4;
    const int tn = tid & 15;

    u64 acc[8][4];
#pragma unroll
    for (int i = 0; i < 8; i++)
#pragma unroll
        for (int j = 0; j < 4; j++) acc[i][j] = 0ull;

    gemm_stage(Ws, Xs, 0, wt, X, 0, tid, HW);
#pragma unroll
    for (int t = 0; t < 8; t++) {
        if (t < 7) {
            gemm_stage(Ws, Xs, (t + 1) & 1, wt, X, (t + 1) * 16, tid, HW);
            CP_WAIT(1);
        } else {
            CP_WAIT(0);
        }
        __syncthreads();
        gemm_compute(Ws, Xs, t & 1, tm, tn, acc);
        __syncthreads();
    }

    const int p0 = pb * 128;
#pragma unroll
    for (int i = 0; i < 8; i++) {
        int o = tm * 8 + i;
        float* dst = outp + ((size_t)b * C + o) * HW + p0;
        float2 f0 = *(float2*)&acc[i][0];
        float2 f1 = *(float2*)&acc[i][1];
        float2 f2 = *(float2*)&acc[i][2];
        float2 f3 = *(float2*)&acc[i][3];
        *(float4*)(dst + tn * 4)      = make_float4(f0.x, f0.y, f1.x, f1.y);
        *(float4*)(dst + 64 + tn * 4) = make_float4(f2.x, f2.y, f3.x, f3.y);
    }
}

extern "C" void kernel_launch(void* const* d_in, const int* in_sizes, int n_in,
                              void* d_out, int out_size)
{
    const float* x     = (const float*)d_in[0];
    const float* wq    = (const float*)d_in[1];
    const float* wk    = (const float*)d_in[2];
    const float* wv    = (const float*)d_in[3];
    const float* wproj = (const float*)d_in[4];
    float* outp = (float*)d_out;

    cudaFuncSetAttribute(attn_kernel,
                         cudaFuncAttributeMaxDynamicSharedMemorySize, ATTN_SMEM);

    wtrans_kernel<<<dim3(64, 4), 256>>>(wq, wk, wv, wproj);
    qkv_kernel<<<dim3(HW / 128, 3, BATCH), 256>>>(x);
    attn_kernel<<<dim3(W / TX, H / TY, HEADS * BATCH), 256, ATTN_SMEM>>>();
    proj_kernel<<<dim3(HW / 128, 1, BATCH), 256>>>(outp);
}

// round 5
// speedup vs baseline: 3.0118x; 1.2742x over previous
#include <cuda_runtime.h>
#include <cuda_bf16.h>
#include <cstdint>

#define BATCH 2
#define C 128
#define H 96
#define W 96
#define HEADS 4
#define DHEAD 32
#define PAD 2
#define INNER 128
#define HW (H * W)
#define HP (H + 2 * PAD)
#define WP (W + 2 * PAD)
#define NTILES (HW / 128)   // 72

typedef unsigned long long u64;

// fp32 scratch
__device__ float g_q[(size_t)BATCH * HW * INNER];          // [b][p][inner]
__device__ float g_kpad[(size_t)BATCH * HP * WP * INNER];  // [b][yp][xp][inner]
__device__ float g_vpad[(size_t)BATCH * HP * WP * INNER];

// bf16 hi/lo operand images
__device__ __nv_bfloat16 g_xhi[(size_t)BATCH * HW * C];    // [b][p][c]
__device__ __nv_bfloat16 g_xlo[(size_t)BATCH * HW * C];
__device__ __nv_bfloat16 g_whi[4 * C * INNER];             // [mat][o][c]
__device__ __nv_bfloat16 g_wlo[4 * C * INNER];
__device__ __nv_bfloat16 g_ohi[(size_t)BATCH * HW * INNER];// [b][p][inner]
__device__ __nv_bfloat16 g_olo[(size_t)BATCH * HW * INNER];

#define FFMA2(d, a, b) \
    asm("fma.rn.f32x2 %0, %1, %2, %0;" : "+l"(d) : "l"(a), "l"(b))
#define PACK2(d, s) \
    asm("mov.b64 %0, {%1, %1};" : "=l"(d) : "f"(s))

__device__ __forceinline__ void cp16(uint32_t smem, const void* g) {
    asm volatile("cp.async.cg.shared.global [%0], [%1], 16;" :: "r"(smem), "l"(g));
}
#define CP_COMMIT() asm volatile("cp.async.commit_group;")
#define CP_WAIT(n)  asm volatile("cp.async.wait_group %0;" :: "n"(n))

__device__ __forceinline__ uint32_t smem_u32(const void* p) {
    uint32_t a;
    asm("{ .reg .u64 t; cvta.to.shared.u64 t, %1; cvt.u32.u64 %0, t; }"
        : "=r"(a) : "l"(p));
    return a;
}

// pack two f32 -> bf16x2 reg, v0 in low half (memory element 0)
#define PACK_BF16X2(res, v0, v1) \
    asm("cvt.rn.bf16x2.f32 %0, %1, %2;" : "=r"(res) : "f"(v1), "f"(v0))

#define LDM_X4(r, addr) \
    asm volatile("ldmatrix.sync.aligned.m8n8.x4.shared.b16 {%0,%1,%2,%3}, [%4];" \
        : "=r"((r)[0]), "=r"((r)[1]), "=r"((r)[2]), "=r"((r)[3]) : "r"(addr))

#define MMA16816(d, a, bp) \
    asm volatile("mma.sync.aligned.m16n8k16.row.col.f32.bf16.bf16.f32 " \
        "{%0,%1,%2,%3}, {%4,%5,%6,%7}, {%8,%9}, {%0,%1,%2,%3};" \
        : "+f"((d)[0]), "+f"((d)[1]), "+f"((d)[2]), "+f"((d)[3]) \
        : "r"((a)[0]), "r"((a)[1]), "r"((a)[2]), "r"((a)[3]), \
          "r"((bp)[0]), "r"((bp)[1]))

// smem tile: 128 rows x 128 bf16, row stride 272B (17*16 -> conflict-free)
#define TROW 272
#define TILE (128 * TROW)
#define GEMM_SMEM (4 * TILE)   // 139264

// ---------------------------------------------------------------------------
// Kernel A: split x (f32 [b][c][p]) -> g_xhi/g_xlo (bf16 [b][p][c])
// grid (HW/32, C/32, B), 256 threads, smem 32x33 transpose
// ---------------------------------------------------------------------------
__global__ __launch_bounds__(256) void xsplit_kernel(const float* __restrict__ x)
{
    __shared__ float t[32][33];
    const int p0 = blockIdx.x * 32, c0 = blockIdx.y * 32, b = blockIdx.z;
    const int tl = threadIdx.x & 31, th = threadIdx.x >> 5;
#pragma unroll
    for (int i = 0; i < 4; i++) {
        int c = th + i * 8;
        t[c][tl] = x[((size_t)b * C + c0 + c) * HW + p0 + tl];
    }
    __syncthreads();
#pragma unroll
    for (int i = 0; i < 4; i++) {
        int p = th + i * 8;
        float v = t[tl][p];
        __nv_bfloat16 hb = __float2bfloat16(v);
        float lov = v - __bfloat162float(hb);
        size_t off = ((size_t)b * HW + p0 + p) * C + c0 + tl;
        g_xhi[off] = hb;
        g_xlo[off] = __float2bfloat16(lov);
    }
}

// ---------------------------------------------------------------------------
// Kernel B: bake weights -> bf16 hi/lo [mat][o][c]
// ---------------------------------------------------------------------------
__global__ __launch_bounds__(256) void wbake_kernel(
    const float* __restrict__ wq, const float* __restrict__ wk,
    const float* __restrict__ wv, const float* __restrict__ wp)
{
    const int mat = blockIdx.y;
    const float* __restrict__ src =
        (mat == 0) ? wq : (mat == 1) ? wk : (mat == 2) ? wv : wp;
    int idx = blockIdx.x * 256 + threadIdx.x;   // 0..16383
    float w = src[idx];
    __nv_bfloat16 hb = __float2bfloat16(w);
    float lov = w - __bfloat162float(hb);
    g_whi[mat * 16384 + idx] = hb;
    g_wlo[mat * 16384 + idx] = __float2bfloat16(lov);
}

// ---------------------------------------------------------------------------
// Shared HMMA mainloop: A tile (M=128 rows) x B tile (N=128 rows), K=128.
// Warp grid 2(m) x 4(n); warp tile 64x32; m16n8k16 bf16.
// ---------------------------------------------------------------------------
__device__ __forceinline__ void mma_tiles(
    uint32_t Abase, uint32_t Bbase, int lane, int mwarp, int nwarp,
    float (*acc)[4])
{
    const uint32_t arow0 = Abase + (uint32_t)(mwarp + (lane & 15)) * TROW
                         + ((lane >> 4) & 1) * 16;
    const uint32_t brow0 = Bbase
                         + (uint32_t)(nwarp + ((lane >> 4) << 3) + (lane & 7)) * TROW
                         + ((lane >> 3) & 1) * 16;
#pragma unroll
    for (int k0 = 0; k0 < 8; k0++) {
        uint32_t a[4][4], bq[2][4];
#pragma unroll
        for (int mt = 0; mt < 4; mt++)
            LDM_X4(a[mt], arow0 + k0 * 32 + mt * (16 * TROW));
#pragma unroll
        for (int n2 = 0; n2 < 2; n2++)
            LDM_X4(bq[n2], brow0 + k0 * 32 + n2 * (16 * TROW));
#pragma unroll
        for (int mt = 0; mt < 4; mt++)
#pragma unroll
            for (int nt = 0; nt < 4; nt++)
                MMA16816(acc[mt * 4 + nt], a[mt], &bq[nt >> 1][(nt & 1) * 2]);
    }
}

// copy one 32KB operand image (128 rows x 256B) into a padded smem tile
__device__ __forceinline__ void stage_tile(
    uint32_t dst, const __nv_bfloat16* __restrict__ src, int tid)
{
    for (int i = tid; i < 2048; i += 256) {
        int r = i >> 4, ch = i & 15;
        cp16(dst + r * TROW + ch * 16, src + r * 128 + ch * 8);
    }
}

// ---------------------------------------------------------------------------
// Kernel 1: QKV. A = X (pixels) hi/lo, B = W hi/lo. D[p][o].
// grid (NTILES, 3, BATCH), 256 threads
// ---------------------------------------------------------------------------
__global__ __launch_bounds__(256) void qkv_mma_kernel()
{
    extern __shared__ char sm[];
    const uint32_t smb = smem_u32(sm);
    const int tid = threadIdx.x, wid = tid >> 5, lane = tid & 31;
    const int pb = blockIdx.x, mat = blockIdx.y, b = blockIdx.z;
    const int p0 = pb * 128;

    const __nv_bfloat16* xh = g_xhi + ((size_t)b * HW + p0) * C;
    const __nv_bfloat16* xl = g_xlo + ((size_t)b * HW + p0) * C;
    const __nv_bfloat16* wh = g_whi + mat * 16384;
    const __nv_bfloat16* wl = g_wlo + mat * 16384;

    stage_tile(smb + 0 * TILE, xh, tid);   // A-hi
    stage_tile(smb + 2 * TILE, wh, tid);   // B-hi
    CP_COMMIT();
    stage_tile(smb + 1 * TILE, xl, tid);   // A-lo
    stage_tile(smb + 3 * TILE, wl, tid);   // B-lo
    CP_COMMIT();

    float acc[16][4];
#pragma unroll
    for (int i = 0; i < 16; i++)
#pragma unroll
        for (int j = 0; j < 4; j++) acc[i][j] = 0.f;

    const int mwarp = (wid >> 2) * 64, nwarp = (wid & 3) * 32;

    CP_WAIT(1);
    __syncthreads();
    mma_tiles(smb + 0 * TILE, smb + 2 * TILE, lane, mwarp, nwarp, acc);  // hi*hi
    CP_WAIT(0);
    __syncthreads();
    mma_tiles(smb + 0 * TILE, smb + 3 * TILE, lane, mwarp, nwarp, acc);  // hi*lo
    mma_tiles(smb + 1 * TILE, smb + 2 * TILE, lane, mwarp, nwarp, acc);  // lo*hi

    // epilogue: D[row=p, col=o]
    const int gid = lane >> 2, tig = lane & 3;
#pragma unroll
    for (int mt = 0; mt < 4; mt++) {
#pragma unroll
        for (int half = 0; half < 2; half++) {
            int r = mwarp + mt * 16 + gid + half * 8;
            int p = p0 + r;
            float* dst;
            if (mat == 0) {
                dst = g_q + ((size_t)b * HW + p) * INNER;
            } else {
                int yy = p / W, xx = p - yy * W;
                float* base = (mat == 1) ? g_kpad : g_vpad;
                dst = base + (((size_t)b * HP + yy + PAD) * WP + (xx + PAD)) * INNER;
            }
#pragma unroll
            for (int nt = 0; nt < 4; nt++) {
                int o = nwarp + nt * 8 + 2 * tig;
                *(float2*)(dst + o) = make_float2(acc[mt * 4 + nt][half * 2],
                                                  acc[mt * 4 + nt][half * 2 + 1]);
            }
        }
    }
}

// ---------------------------------------------------------------------------
// Kernel 2: window attention (fp32, smem-tiled, f32x2); emits bf16 hi/lo
// pixel-major [b][p][inner] for proj's B operand.
// ---------------------------------------------------------------------------
#define TX 32
#define TY 8
#define PWT (TX + 4)
#define PHT (TY + 4)
#define NPIX (PWT * PHT)
#define DGS 433
#define ATTN_SMEM (2 * 8 * DGS * 16)

__global__ __launch_bounds__(256) void attn_kernel()
{
    extern __shared__ float4 sm4[];
    float4* ks4 = sm4;
    float4* vs4 = sm4 + 8 * DGS;

    const int t  = threadIdx.x;
    const int x0 = blockIdx.x * TX;
    const int y0 = blockIdx.y * TY;
    const int h  = blockIdx.z & 3;
    const int b  = blockIdx.z >> 2;

    const float* __restrict__ kg =
        g_kpad + (((size_t)b * HP + y0) * WP + x0) * INNER + h * DHEAD;
    const float* __restrict__ vg =
        g_vpad + (((size_t)b * HP + y0) * WP + x0) * INNER + h * DHEAD;

#pragma unroll
    for (int i = t; i < NPIX * 8; i += 256) {
        int pp = i >> 3, dg = i & 7;
        int py = pp / PWT, px = pp - py * PWT;
        size_t goff = ((size_t)py * WP + px) * INNER + dg * 4;
        ks4[dg * DGS + pp] = *(const float4*)(kg + goff);
        vs4[dg * DGS + pp] = *(const float4*)(vg + goff);
    }

    const int tx = t & 31, ty = t >> 5;
    const int p = (y0 + ty) * W + x0 + tx;
    u64 q2[16];
    const float* qp = g_q + ((size_t)b * HW + p) * INNER + h * DHEAD;
#pragma unroll
    for (int dg = 0; dg < 8; dg++) {
        ulonglong2 v = *(const ulonglong2*)(qp + dg * 4);
        q2[dg * 2] = v.x; q2[dg * 2 + 1] = v.y;
    }

    __syncthreads();

    const float scale = 0.17677669529663687f;
    float sc[25];
#pragma unroll
    for (int n = 0; n < 25; n++) {
        const int di = n / 5, dj = n - 5 * (n / 5);
        const int pix = (ty + di) * PWT + (tx + dj);
        u64 s2 = 0ull;
#pragma unroll
        for (int dg = 0; dg < 8; dg++) {
            ulonglong2 kv = *(const ulonglong2*)&ks4[dg * DGS + pix];
            FFMA2(s2, q2[dg * 2], kv.x);
            FFMA2(s2, q2[dg * 2 + 1], kv.y);
        }
        float2 sf = *(float2*)&s2;
        sc[n] = (sf.x + sf.y) * scale;
    }

    float m = sc[0];
#pragma unroll
    for (int n = 1; n < 25; n++) m = fmaxf(m, sc[n]);
    float sum = 0.f;
#pragma unroll
    for (int n = 0; n < 25; n++) {
        float e = __expf(sc[n] - m);
        sc[n] = e;
        sum += e;
    }
    const float inv = 1.f / sum;

    u64 o2[16];
#pragma unroll
    for (int i = 0; i < 16; i++) o2[i] = 0ull;
#pragma unroll
    for (int n = 0; n < 25; n++) {
        const int di = n / 5, dj = n - 5 * (n / 5);
        const int pix = (ty + di) * PWT + (tx + dj);
        u64 w2;
        PACK2(w2, sc[n]);
#pragma unroll
        for (int dg = 0; dg < 8; dg++) {
            ulonglong2 vv = *(const ulonglong2*)&vs4[dg * DGS + pix];
            FFMA2(o2[dg * 2], w2, vv.x);
            FFMA2(o2[dg * 2 + 1], w2, vv.y);
        }
    }

    // split to bf16 hi/lo, write pixel-major
    uint32_t hu[16], lu[16];
#pragma unroll
    for (int i = 0; i < 16; i++) {
        float2 f = *(float2*)&o2[i];
        float a = f.x * inv, bb = f.y * inv;
        __nv_bfloat16 ha = __float2bfloat16(a), hb = __float2bfloat16(bb);
        float la = a - __bfloat162float(ha);
        float lb = bb - __bfloat162float(hb);
        PACK_BF16X2(hu[i], a, bb);
        PACK_BF16X2(lu[i], la, lb);
    }
    __nv_bfloat16* oh = g_ohi + ((size_t)b * HW + p) * INNER + h * DHEAD;
    __nv_bfloat16* ol = g_olo + ((size_t)b * HW + p) * INNER + h * DHEAD;
#pragma unroll
    for (int cc = 0; cc < 4; cc++) {
        *(uint4*)(oh + cc * 8) = make_uint4(hu[4 * cc], hu[4 * cc + 1],
                                            hu[4 * cc + 2], hu[4 * cc + 3]);
        *(uint4*)(ol + cc * 8) = make_uint4(lu[4 * cc], lu[4 * cc + 1],
                                            lu[4 * cc + 2], lu[4 * cc + 3]);
    }
}

// ---------------------------------------------------------------------------
// Kernel 3: proj. A = wproj (M=c_out) hi/lo, B = attn-out (N=pixels) hi/lo.
// D[c][p] -> NCHW output. grid (NTILES, BATCH), 256 threads
// ---------------------------------------------------------------------------
__global__ __launch_bounds__(256) void proj_mma_kernel(float* __restrict__ outp)
{
    extern __shared__ char sm[];
    const uint32_t smb = smem_u32(sm);
    const int tid = threadIdx.x, wid = tid >> 5, lane = tid & 31;
    const int pb = blockIdx.x, b = blockIdx.y;
    const int p0 = pb * 128;

    const __nv_bfloat16* ah = g_whi + 3 * 16384;
    const __nv_bfloat16* al = g_wlo + 3 * 16384;
    const __nv_bfloat16* bh = g_ohi + ((size_t)b * HW + p0) * INNER;
    const __nv_bfloat16* bl = g_olo + ((size_t)b * HW + p0) * INNER;

    stage_tile(smb + 0 * TILE, ah, tid);
    stage_tile(smb + 2 * TILE, bh, tid);
    CP_COMMIT();
    stage_tile(smb + 1 * TILE, al, tid);
    stage_tile(smb + 3 * TILE, bl, tid);
    CP_COMMIT();

    float acc[16][4];
#pragma unroll
    for (int i = 0; i < 16; i++)
#pragma unroll
        for (int j = 0; j < 4; j++) acc[i][j] = 0.f;

    const int mwarp = (wid >> 2) * 64, nwarp = (wid & 3) * 32;

    CP_WAIT(1);
    __syncthreads();
    mma_tiles(smb + 0 * TILE, smb + 2 * TILE, lane, mwarp, nwarp, acc);  // hi*hi
    CP_WAIT(0);
    __syncthreads();
    mma_tiles(smb + 0 * TILE, smb + 3 * TILE, lane, mwarp, nwarp, acc);  // hi*lo
    mma_tiles(smb + 1 * TILE, smb + 2 * TILE, lane, mwarp, nwarp, acc);  // lo*hi

    // epilogue: D[row=c_out, col=p]
    const int gid = lane >> 2, tig = lane & 3;
#pragma unroll
    for (int mt = 0; mt < 4; mt++) {
#pragma unroll
        for (int half = 0; half < 2; half++) {
            int c = mwarp + mt * 16 + gid + half * 8;
            float* dst = outp + ((size_t)b * C + c) * HW + p0;
#pragma unroll
            for (int nt = 0; nt < 4; nt++) {
                int col = nwarp + nt * 8 + 2 * tig;
                *(float2*)(dst + col) = make_float2(acc[mt * 4 + nt][half * 2],
                                                    acc[mt * 4 + nt][half * 2 + 1]);
            }
        }
    }
}

extern "C" void kernel_launch(void* const* d_in, const int* in_sizes, int n_in,
                              void* d_out, int out_size)
{
    const float* x     = (const float*)d_in[0];
    const float* wq    = (const float*)d_in[1];
    const float* wk    = (const float*)d_in[2];
    const float* wv    = (const float*)d_in[3];
    const float* wproj = (const float*)d_in[4];
    float* outp = (float*)d_out;

    cudaFuncSetAttribute(attn_kernel,
                         cudaFuncAttributeMaxDynamicSharedMemorySize, ATTN_SMEM);
    cudaFuncSetAttribute(qkv_mma_kernel,
                         cudaFuncAttributeMaxDynamicSharedMemorySize, GEMM_SMEM);
    cudaFuncSetAttribute(proj_mma_kernel,
                         cudaFuncAttributeMaxDynamicSharedMemorySize, GEMM_SMEM);

    wbake_kernel<<<dim3(64, 4), 256>>>(wq, wk, wv, wproj);
    xsplit_kernel<<<dim3(HW / 32, C / 32, BATCH), 256>>>(x);
    qkv_mma_kernel<<<dim3(NTILES, 3, BATCH), 256, GEMM_SMEM>>>();
    attn_kernel<<<dim3(W / TX, H / TY, HEADS * BATCH), 256, ATTN_SMEM>>>();
    proj_mma_kernel<<<dim3(NTILES, BATCH), 256, GEMM_SMEM>>>(outp);
}